// round 16
// baseline (speedup 1.0000x reference)
#include <cuda_runtime.h>

#define SEQ    2048
#define DIM    256
#define NHEAD  8
#define NBATCH 8
#define NROWS  (NBATCH*SEQ)     // 16384
#define HBTOT  (NHEAD*NBATCH)   // 64

typedef unsigned long long ull;

// scratch: q,k,v  each [H*B][S][D] fp32 = 128 MB
__device__ float g_q[(size_t)HBTOT*SEQ*DIM];
__device__ float g_k[(size_t)HBTOT*SEQ*DIM];
__device__ float g_v[(size_t)HBTOT*SEQ*DIM];

// ---------------------------------------------------------------------------
// packed f32x2 helpers (FFMA2 path: only reachable via PTX fma.rn.f32x2)
// ---------------------------------------------------------------------------
__device__ __forceinline__ ull pk2(float lo, float hi) {
    ull r; asm("mov.b64 %0, {%1,%2};" : "=l"(r) : "f"(lo), "f"(hi)); return r;
}
__device__ __forceinline__ void upk2(ull v, float& lo, float& hi) {
    asm("mov.b64 {%0,%1}, %2;" : "=f"(lo), "=f"(hi) : "l"(v));
}
__device__ __forceinline__ ull ffma2(ull a, ull b, ull c) {
    ull d; asm("fma.rn.f32x2 %0, %1, %2, %3;" : "=l"(d) : "l"(a), "l"(b), "l"(c));
    return d;
}
__device__ __forceinline__ ull fmul2(ull a, ull b) {
    ull d; asm("mul.rn.f32x2 %0, %1, %2;" : "=l"(d) : "l"(a), "l"(b));
    return d;
}
__device__ __forceinline__ void cpa16(void* dst, const void* src) {
    unsigned s = (unsigned)__cvta_generic_to_shared(dst);
    asm volatile("cp.async.cg.shared.global [%0], [%1], 16;" :: "r"(s), "l"(src));
}

// ---------------------------------------------------------------------------
// Kernel 0: init output with bias (flash accumulates into it atomically)
// ---------------------------------------------------------------------------
__global__ __launch_bounds__(256) void init_out_kernel(
    const float* __restrict__ Cb, float* __restrict__ out)
{
    int idx = blockIdx.x * 256 + threadIdx.x;     // 0..131071
    out[idx] = Cb[idx & 7];
}

// ---------------------------------------------------------------------------
// Kernel 1: QKV projections (R9 compute — best measured), 4-head chunks.
// grid (4 n-tiles, 256 m-tiles, 12 = 3 types x 4 heads), block 16x16,
// 64x64 tile, 32-wide K chunks, cp.async double-buffered.
// ---------------------------------------------------------------------------
__global__ __launch_bounds__(256) void proj_kernel(
    const float* __restrict__ x, const float* __restrict__ lstm,
    const float* __restrict__ Qw, const float* __restrict__ Qb,
    const float* __restrict__ Kw, const float* __restrict__ Kb,
    const float* __restrict__ Vw, const float* __restrict__ Vb,
    int h0)
{
    __shared__ float As[2][64][32];   // [buf][row][k]
    __shared__ float Bs[2][32][64];   // [buf][k][col]

    const int bz = blockIdx.z;
    const int type = bz >> 2, h = (bz & 3) + h0;
    const float* A; const float* W; const float* bias; float* out;
    if (type == 0)      { A = lstm; W = Qw; bias = Qb; out = g_q; }
    else if (type == 1) { A = x;    W = Kw; bias = Kb; out = g_k; }
    else                { A = x;    W = Vw; bias = Vb; out = g_v; }
    W    += h * DIM * DIM;
    bias += h * DIM;
    out  += (size_t)h * NROWS * DIM;

    const int r0 = blockIdx.y * 64, d0 = blockIdx.x * 64;
    const int tx = threadIdx.x, ty = threadIdx.y;
    const int tid = ty * 16 + tx;

    // cp.async load of one 64x32 A chunk + 32x64 B chunk into buffer `buf`
    auto load_chunk = [&](int buf, int kt) {
        #pragma unroll
        for (int i = 0; i < 2; i++) {
            int u = tid + i * 256;                // 0..511
            int ar = u >> 3, as = (u & 7) * 4;    // A: row, 4-float seg
            cpa16(&As[buf][ar][as],
                  &A[(size_t)(r0 + ar) * DIM + kt + as]);
            int br = u >> 4, bs = (u & 15) * 4;   // B: k-row, 4-float seg
            cpa16(&Bs[buf][br][bs],
                  &W[(size_t)(kt + br) * DIM + d0 + bs]);
        }
    };

    ull acc[4][2];
    #pragma unroll
    for (int i = 0; i < 4; i++) { acc[i][0] = 0ull; acc[i][1] = 0ull; }

    load_chunk(0, 0);
    asm volatile("cp.async.commit_group;");

    int buf = 0;
    for (int ck = 0; ck < 8; ck++) {
        if (ck + 1 < 8) {
            load_chunk(buf ^ 1, (ck + 1) * 32);
            asm volatile("cp.async.commit_group;");
            asm volatile("cp.async.wait_group 1;");
        } else {
            asm volatile("cp.async.wait_group 0;");
        }
        __syncthreads();

        #pragma unroll
        for (int kk = 0; kk < 32; kk++) {
            float a0 = As[buf][ty * 4 + 0][kk];
            float a1 = As[buf][ty * 4 + 1][kk];
            float a2 = As[buf][ty * 4 + 2][kk];
            float a3 = As[buf][ty * 4 + 3][kk];
            ulonglong2 bv = *(const ulonglong2*)&Bs[buf][kk][tx * 4];
            ull p0 = pk2(a0, a0), p1 = pk2(a1, a1);
            ull p2 = pk2(a2, a2), p3 = pk2(a3, a3);
            acc[0][0] = ffma2(p0, bv.x, acc[0][0]);
            acc[0][1] = ffma2(p0, bv.y, acc[0][1]);
            acc[1][0] = ffma2(p1, bv.x, acc[1][0]);
            acc[1][1] = ffma2(p1, bv.y, acc[1][1]);
            acc[2][0] = ffma2(p2, bv.x, acc[2][0]);
            acc[2][1] = ffma2(p2, bv.y, acc[2][1]);
            acc[3][0] = ffma2(p3, bv.x, acc[3][0]);
            acc[3][1] = ffma2(p3, bv.y, acc[3][1]);
        }
        __syncthreads();   // compute done before buf is overwritten next iter
        buf ^= 1;
    }

    #pragma unroll
    for (int i = 0; i < 4; i++) {
        float4 o;
        upk2(acc[i][0], o.x, o.y);
        upk2(acc[i][1], o.z, o.w);
        o.x += bias[d0 + tx * 4 + 0];
        o.y += bias[d0 + tx * 4 + 1];
        o.z += bias[d0 + tx * 4 + 2];
        o.w += bias[d0 + tx * 4 + 3];
        *(float4*)&out[(size_t)(r0 + ty * 4 + i) * DIM + d0 + tx * 4] = o;
    }
}

// ---------------------------------------------------------------------------
// Kernel 2: flash attention, 128-wide K tiles (4 score cols per lane).
// Delta vs R13: (a) hb0 param for 4-head chunking; (b) sparse phase tests
// activity with ONE ballot (exactly equivalent to the old warp-max test);
// the 5-shfl max reduce runs only inside the rare active branch.
// All arithmetic bit-identical to R13.
// ---------------------------------------------------------------------------
#define FLASH_SMEM ((64*256 + 128*256) * 4)   // Q 64KB + K 128KB = 196608

__global__ __launch_bounds__(256, 1) void flash_kernel(
    const float* __restrict__ Cw, float* __restrict__ out, int hb0)
{
    extern __shared__ float sm[];
    float* Qs = sm;               // [64][256] linear
    float* Ks = sm + 64 * 256;    // [128][256] xor-swizzled rows (tile cols)

    const int qt = blockIdx.x;    // 0..31
    const int hb = blockIdx.y + hb0;
    const size_t base = (size_t)hb * SEQ * DIM;
    const int tid = threadIdx.x;
    const int w = tid >> 5, c = tid & 31;
    const int cx = c & 7;

    // K tile load: 128 rows x 64 float4 = 8192 tasks, 32 per thread
    auto load_ktile = [&](int kt) {
        #pragma unroll
        for (int i = 0; i < 32; i++) {
            int u = tid + i * 256;
            int r = u >> 6, k4 = u & 63;
            cpa16(&Ks[r * 256 + ((k4 ^ (r & 7)) << 2)],
                  &g_k[base + (size_t)(kt * 128 + r) * DIM + k4 * 4]);
        }
        asm volatile("cp.async.commit_group;");
    };

    // prefetch K tile 0 (async), then load Q tile 64x256
    load_ktile(0);
    #pragma unroll
    for (int i = 0; i < 16; i++) {
        int u = tid + i * 256;
        int r = u >> 6, k4 = u & 63;
        *(float4*)&Qs[r * 256 + k4 * 4] =
            *(const float4*)&g_q[base + (size_t)(qt * 64 + r) * DIM + k4 * 4];
    }

    ull o[8][4];                  // packed pairs covering dims 8c..8c+7
    #pragma unroll
    for (int i = 0; i < 8; i++)
        #pragma unroll
        for (int j = 0; j < 4; j++) o[i][j] = 0ull;
    float m[8], l[8];
    #pragma unroll
    for (int i = 0; i < 8; i++) { m[i] = -3.0e38f; l[i] = 0.f; }

    for (int kt = 0; kt < SEQ / 128; kt++) {
        asm volatile("cp.async.wait_group 0;");
        __syncthreads();          // tile kt (and Q on iter 0) visible

        // dense QK: lane computes s[rr][cols c, c+32, c+64, c+96]
        ull acc[8][4];
        #pragma unroll
        for (int rr = 0; rr < 8; rr++)
            #pragma unroll
            for (int j = 0; j < 4; j++) acc[rr][j] = 0ull;

        const float* kp0 = &Ks[c * 256];
        const float* kp1 = &Ks[(c + 32) * 256];   // same xor phase: &7 equal
        const float* kp2 = &Ks[(c + 64) * 256];
        const float* kp3 = &Ks[(c + 96) * 256];
        #pragma unroll 2
        for (int k4 = 0; k4 < 64; k4++) {
            int sc = (k4 ^ cx) << 2;
            ulonglong2 kv0 = *(const ulonglong2*)&kp0[sc];
            ulonglong2 kv1 = *(const ulonglong2*)&kp1[sc];
            ulonglong2 kv2 = *(const ulonglong2*)&kp2[sc];
            ulonglong2 kv3 = *(const ulonglong2*)&kp3[sc];
            #pragma unroll
            for (int rr = 0; rr < 8; rr++) {
                ulonglong2 qv = *(const ulonglong2*)&Qs[(w * 8 + rr) * 256 + k4 * 4];
                acc[rr][0] = ffma2(qv.x, kv0.x, acc[rr][0]);
                acc[rr][0] = ffma2(qv.y, kv0.y, acc[rr][0]);
                acc[rr][1] = ffma2(qv.x, kv1.x, acc[rr][1]);
                acc[rr][1] = ffma2(qv.y, kv1.y, acc[rr][1]);
                acc[rr][2] = ffma2(qv.x, kv2.x, acc[rr][2]);
                acc[rr][2] = ffma2(qv.y, kv2.y, acc[rr][2]);
                acc[rr][3] = ffma2(qv.x, kv3.x, acc[rr][3]);
                acc[rr][3] = ffma2(qv.y, kv3.y, acc[rr][3]);
            }
        }

        __syncthreads();          // all warps done reading Ks
        if (kt + 1 < SEQ / 128)
            load_ktile(kt + 1);   // overlaps the sparse phase below

        // sparse softmax + PV gather, per row (reads only regs + g_v)
        const float* vtile = &g_v[base + (size_t)(kt * 128) * DIM + c * 8];
        #pragma unroll
        for (int rr = 0; rr < 8; rr++) {
            float a, b;
            float s[4];
            upk2(acc[rr][0], a, b); s[0] = (a + b) * 0.0625f;
            upk2(acc[rr][1], a, b); s[1] = (a + b) * 0.0625f;
            upk2(acc[rr][2], a, b); s[2] = (a + b) * 0.0625f;
            upk2(acc[rr][3], a, b); s[3] = (a + b) * 0.0625f;

            // activity test: any s >= m-35 anywhere in warp  <=>  tm >= m-35
            float thr0 = m[rr] - 35.0f;
            bool cnd = (s[0] >= thr0) | (s[1] >= thr0) |
                       (s[2] >= thr0) | (s[3] >= thr0);
            if (__ballot_sync(0xffffffffu, cnd)) {        // warp-uniform
                float tm = fmaxf(fmaxf(s[0], s[1]), fmaxf(s[2], s[3]));
                #pragma unroll
                for (int off = 16; off > 0; off >>= 1)
                    tm = fmaxf(tm, __shfl_xor_sync(0xffffffffu, tm, off));
                float nm = fmaxf(m[rr], tm);
                if (nm > m[rr]) {                 // rescale only on max update
                    float fac = __expf(m[rr] - nm);
                    l[rr] *= fac;
                    ull f2 = pk2(fac, fac);
                    o[rr][0] = fmul2(o[rr][0], f2);
                    o[rr][1] = fmul2(o[rr][1], f2);
                    o[rr][2] = fmul2(o[rr][2], f2);
                    o[rr][3] = fmul2(o[rr][3], f2);
                    m[rr] = nm;
                }
                float thr = nm - 35.0f;
                #pragma unroll
                for (int j = 0; j < 4; j++) {
                    unsigned bal = __ballot_sync(0xffffffffu, s[j] >= thr);
                    while (bal) {
                        int ln = __ffs(bal) - 1; bal &= bal - 1;
                        float sv = __shfl_sync(0xffffffffu, s[j], ln);
                        float p = __expf(sv - nm);
                        l[rr] += p;
                        const ulonglong2* vr =
                            (const ulonglong2*)(vtile + (size_t)(ln + j * 32) * DIM);
                        ulonglong2 V0 = vr[0], V1 = vr[1];
                        ull pp = pk2(p, p);
                        o[rr][0] = ffma2(pp, V0.x, o[rr][0]);
                        o[rr][1] = ffma2(pp, V0.y, o[rr][1]);
                        o[rr][2] = ffma2(pp, V1.x, o[rr][2]);
                        o[rr][3] = ffma2(pp, V1.y, o[rr][3]);
                    }
                }
            }
        }
    }

    // ------------------------------------------------------------------
    // fused epilogue: out[r,n] += sum_d o_norm[r,d] * Cw[h*256+d, n]
    // ------------------------------------------------------------------
    const int h = hb >> 3;
    const int out_r0 = (hb & 7) * SEQ + qt * 64 + w * 8;

    float cw[8][8];               // [i dim-in-slice][n]
    const float* cwp = Cw + ((size_t)h * 256 + c * 8) * 8;
    #pragma unroll
    for (int i = 0; i < 8; i++) {
        float4 u0 = *(const float4*)&cwp[i * 8 + 0];
        float4 u1 = *(const float4*)&cwp[i * 8 + 4];
        cw[i][0] = u0.x; cw[i][1] = u0.y; cw[i][2] = u0.z; cw[i][3] = u0.w;
        cw[i][4] = u1.x; cw[i][5] = u1.y; cw[i][6] = u1.z; cw[i][7] = u1.w;
    }

    #pragma unroll
    for (int rr = 0; rr < 8; rr++) {
        float inv = 1.0f / l[rr];
        float v[8];
        upk2(o[rr][0], v[0], v[1]);
        upk2(o[rr][1], v[2], v[3]);
        upk2(o[rr][2], v[4], v[5]);
        upk2(o[rr][3], v[6], v[7]);
        float pn[8] = {};
        #pragma unroll
        for (int i = 0; i < 8; i++) {
            float ov = v[i] * inv;
            #pragma unroll
            for (int n = 0; n < 8; n++)
                pn[n] = fmaf(ov, cw[i][n], pn[n]);
        }
        #pragma unroll
        for (int n = 0; n < 8; n++) {
            #pragma unroll
            for (int off = 16; off > 0; off >>= 1)
                pn[n] += __shfl_xor_sync(0xffffffffu, pn[n], off);
        }
        if (c < 8)
            atomicAdd(&out[(size_t)(out_r0 + rr) * 8 + c], pn[c]);
    }
}

// ---------------------------------------------------------------------------
// Launch: fork-join across two streams so proj(heads 4-7) overlaps
// flash(heads 0-3).  Streams/events are created lazily on the first
// (eager, pre-capture) call; the captured work is identical every call.
// ---------------------------------------------------------------------------
static cudaStream_t g_s2 = 0;
static cudaEvent_t  g_evA = 0, g_ev1 = 0, g_ev2 = 0;

extern "C" void kernel_launch(void* const* d_in, const int* in_sizes, int n_in,
                              void* d_out, int out_size)
{
    const float* x    = (const float*)d_in[0];
    const float* lstm = (const float*)d_in[1];
    const float* Qw   = (const float*)d_in[2];
    const float* Qb   = (const float*)d_in[3];
    const float* Kw   = (const float*)d_in[4];
    const float* Kb   = (const float*)d_in[5];
    const float* Vw   = (const float*)d_in[6];
    const float* Vb   = (const float*)d_in[7];
    const float* Cw   = (const float*)d_in[8];
    const float* Cb   = (const float*)d_in[9];
    float* out = (float*)d_out;

    if (!g_s2) {
        cudaStreamCreateWithFlags(&g_s2, cudaStreamNonBlocking);
        cudaEventCreateWithFlags(&g_evA, cudaEventDisableTiming);
        cudaEventCreateWithFlags(&g_ev1, cudaEventDisableTiming);
        cudaEventCreateWithFlags(&g_ev2, cudaEventDisableTiming);
        cudaFuncSetAttribute(flash_kernel,
                             cudaFuncAttributeMaxDynamicSharedMemorySize,
                             FLASH_SMEM);
    }

    // legacy stream: init out with bias
    init_out_kernel<<<512, 256>>>(Cb, out);
    cudaEventRecord(g_evA, 0);

    // side stream: proj heads 0-3, then heads 4-7
    cudaStreamWaitEvent(g_s2, g_evA, 0);
    proj_kernel<<<dim3(4, 256, 12), dim3(16, 16), 0, g_s2>>>(
        x, lstm, Qw, Qb, Kw, Kb, Vw, Vb, 0);
    cudaEventRecord(g_ev1, g_s2);
    proj_kernel<<<dim3(4, 256, 12), dim3(16, 16), 0, g_s2>>>(
        x, lstm, Qw, Qb, Kw, Kb, Vw, Vb, 4);
    cudaEventRecord(g_ev2, g_s2);

    // legacy stream: flash chunk h0-3 (overlaps proj chunk h4-7), then h4-7
    cudaStreamWaitEvent(0, g_ev1, 0);
    flash_kernel<<<dim3(32, 32), 256, FLASH_SMEM>>>(Cw, out, 0);
    cudaStreamWaitEvent(0, g_ev2, 0);
    flash_kernel<<<dim3(32, 32), 256, FLASH_SMEM>>>(Cw, out, 32);
}

// round 17
// speedup vs baseline: 1.0178x; 1.0178x over previous
#include <cuda_runtime.h>

#define SEQ    2048
#define DIM    256
#define NHEAD  8
#define NBATCH 8
#define NROWS  (NBATCH*SEQ)     // 16384
#define HBTOT  (NHEAD*NBATCH)   // 64

typedef unsigned long long ull;

// scratch: q,k,v  each [H*B][S][D] fp32 = 128 MB
__device__ float g_q[(size_t)HBTOT*SEQ*DIM];
__device__ float g_k[(size_t)HBTOT*SEQ*DIM];
__device__ float g_v[(size_t)HBTOT*SEQ*DIM];

// ---------------------------------------------------------------------------
// packed f32x2 helpers (FFMA2 path: only reachable via PTX fma.rn.f32x2)
// ---------------------------------------------------------------------------
__device__ __forceinline__ ull pk2(float lo, float hi) {
    ull r; asm("mov.b64 %0, {%1,%2};" : "=l"(r) : "f"(lo), "f"(hi)); return r;
}
__device__ __forceinline__ void upk2(ull v, float& lo, float& hi) {
    asm("mov.b64 {%0,%1}, %2;" : "=f"(lo), "=f"(hi) : "l"(v));
}
__device__ __forceinline__ ull ffma2(ull a, ull b, ull c) {
    ull d; asm("fma.rn.f32x2 %0, %1, %2, %3;" : "=l"(d) : "l"(a), "l"(b), "l"(c));
    return d;
}
__device__ __forceinline__ ull fmul2(ull a, ull b) {
    ull d; asm("mul.rn.f32x2 %0, %1, %2;" : "=l"(d) : "l"(a), "l"(b));
    return d;
}
__device__ __forceinline__ void cpa16(void* dst, const void* src) {
    unsigned s = (unsigned)__cvta_generic_to_shared(dst);
    asm volatile("cp.async.cg.shared.global [%0], [%1], 16;" :: "r"(s), "l"(src));
}

// ---------------------------------------------------------------------------
// Kernel 0: init output with bias (flash accumulates into it atomically)
// ---------------------------------------------------------------------------
__global__ __launch_bounds__(256) void init_out_kernel(
    const float* __restrict__ Cb, float* __restrict__ out)
{
    int idx = blockIdx.x * 256 + threadIdx.x;     // 0..131071
    out[idx] = Cb[idx & 7];
}

// ---------------------------------------------------------------------------
// Kernel 1: QKV projections.  out[h,r,d] = sum_f A[r,f]*W[h,f,d] + b[h,d]
// grid (4 n-tiles, 256 m-tiles, 24 matrices), block 16x16, 64x64 tile,
// 32-wide K chunks, cp.async double-buffered (R9 structure).
// Delta vs R9: A read from smem as float4 ALONG kk (contiguous, aligned) —
// 128 scalar LDS per warp-chunk collapse to 32 LDS.128, dropping smem
// wavefronts below the fma-pipe demand.  FFMA2 order (kk ascending) is
// bit-identical to R9; storage layout and load paths unchanged.
// ---------------------------------------------------------------------------
__global__ __launch_bounds__(256) void proj_kernel(
    const float* __restrict__ x, const float* __restrict__ lstm,
    const float* __restrict__ Qw, const float* __restrict__ Qb,
    const float* __restrict__ Kw, const float* __restrict__ Kb,
    const float* __restrict__ Vw, const float* __restrict__ Vb)
{
    __shared__ float As[2][64][32];   // [buf][row][k]
    __shared__ float Bs[2][32][64];   // [buf][k][col]

    const int bz = blockIdx.z;
    const int type = bz >> 3, h = bz & 7;
    const float* A; const float* W; const float* bias; float* out;
    if (type == 0)      { A = lstm; W = Qw; bias = Qb; out = g_q; }
    else if (type == 1) { A = x;    W = Kw; bias = Kb; out = g_k; }
    else                { A = x;    W = Vw; bias = Vb; out = g_v; }
    W    += h * DIM * DIM;
    bias += h * DIM;
    out  += (size_t)h * NROWS * DIM;

    const int r0 = blockIdx.y * 64, d0 = blockIdx.x * 64;
    const int tx = threadIdx.x, ty = threadIdx.y;
    const int tid = ty * 16 + tx;

    // cp.async load of one 64x32 A chunk + 32x64 B chunk into buffer `buf`
    auto load_chunk = [&](int buf, int kt) {
        #pragma unroll
        for (int i = 0; i < 2; i++) {
            int u = tid + i * 256;                // 0..511
            int ar = u >> 3, as = (u & 7) * 4;    // A: row, 4-float seg
            cpa16(&As[buf][ar][as],
                  &A[(size_t)(r0 + ar) * DIM + kt + as]);
            int br = u >> 4, bs = (u & 15) * 4;   // B: k-row, 4-float seg
            cpa16(&Bs[buf][br][bs],
                  &W[(size_t)(kt + br) * DIM + d0 + bs]);
        }
    };

    ull acc[4][2];
    #pragma unroll
    for (int i = 0; i < 4; i++) { acc[i][0] = 0ull; acc[i][1] = 0ull; }

    load_chunk(0, 0);
    asm volatile("cp.async.commit_group;");

    int buf = 0;
    for (int ck = 0; ck < 8; ck++) {
        if (ck + 1 < 8) {
            load_chunk(buf ^ 1, (ck + 1) * 32);
            asm volatile("cp.async.commit_group;");
            asm volatile("cp.async.wait_group 1;");
        } else {
            asm volatile("cp.async.wait_group 0;");
        }
        __syncthreads();

        #pragma unroll
        for (int kk4 = 0; kk4 < 8; kk4++) {
            float4 A0 = *(const float4*)&As[buf][ty * 4 + 0][kk4 * 4];
            float4 A1 = *(const float4*)&As[buf][ty * 4 + 1][kk4 * 4];
            float4 A2 = *(const float4*)&As[buf][ty * 4 + 2][kk4 * 4];
            float4 A3 = *(const float4*)&As[buf][ty * 4 + 3][kk4 * 4];
            const float* f0 = &A0.x;
            const float* f1 = &A1.x;
            const float* f2 = &A2.x;
            const float* f3 = &A3.x;
            #pragma unroll
            for (int j = 0; j < 4; j++) {
                ulonglong2 bv = *(const ulonglong2*)&Bs[buf][kk4 * 4 + j][tx * 4];
                ull p0 = pk2(f0[j], f0[j]), p1 = pk2(f1[j], f1[j]);
                ull p2 = pk2(f2[j], f2[j]), p3 = pk2(f3[j], f3[j]);
                acc[0][0] = ffma2(p0, bv.x, acc[0][0]);
                acc[0][1] = ffma2(p0, bv.y, acc[0][1]);
                acc[1][0] = ffma2(p1, bv.x, acc[1][0]);
                acc[1][1] = ffma2(p1, bv.y, acc[1][1]);
                acc[2][0] = ffma2(p2, bv.x, acc[2][0]);
                acc[2][1] = ffma2(p2, bv.y, acc[2][1]);
                acc[3][0] = ffma2(p3, bv.x, acc[3][0]);
                acc[3][1] = ffma2(p3, bv.y, acc[3][1]);
            }
        }
        __syncthreads();   // compute done before buf is overwritten next iter
        buf ^= 1;
    }

    #pragma unroll
    for (int i = 0; i < 4; i++) {
        float4 o;
        upk2(acc[i][0], o.x, o.y);
        upk2(acc[i][1], o.z, o.w);
        o.x += bias[d0 + tx * 4 + 0];
        o.y += bias[d0 + tx * 4 + 1];
        o.z += bias[d0 + tx * 4 + 2];
        o.w += bias[d0 + tx * 4 + 3];
        *(float4*)&out[(size_t)(r0 + ty * 4 + i) * DIM + d0 + tx * 4] = o;
    }
}

// ---------------------------------------------------------------------------
// Kernel 2: flash attention, 128-wide K tiles (4 score cols per lane).
// (byte-identical to R13 — protect the win)
// ---------------------------------------------------------------------------
#define FLASH_SMEM ((64*256 + 128*256) * 4)   // Q 64KB + K 128KB = 196608

__global__ __launch_bounds__(256, 1) void flash_kernel(
    const float* __restrict__ Cw, float* __restrict__ out)
{
    extern __shared__ float sm[];
    float* Qs = sm;               // [64][256] linear
    float* Ks = sm + 64 * 256;    // [128][256] xor-swizzled rows (tile cols)

    const int qt = blockIdx.x;    // 0..31
    const int hb = blockIdx.y;    // 0..63
    const size_t base = (size_t)hb * SEQ * DIM;
    const int tid = threadIdx.x;
    const int w = tid >> 5, c = tid & 31;
    const int cx = c & 7;

    // K tile load: 128 rows x 64 float4 = 8192 tasks, 32 per thread
    auto load_ktile = [&](int kt) {
        #pragma unroll
        for (int i = 0; i < 32; i++) {
            int u = tid + i * 256;
            int r = u >> 6, k4 = u & 63;
            cpa16(&Ks[r * 256 + ((k4 ^ (r & 7)) << 2)],
                  &g_k[base + (size_t)(kt * 128 + r) * DIM + k4 * 4]);
        }
        asm volatile("cp.async.commit_group;");
    };

    // prefetch K tile 0 (async), then load Q tile 64x256
    load_ktile(0);
    #pragma unroll
    for (int i = 0; i < 16; i++) {
        int u = tid + i * 256;
        int r = u >> 6, k4 = u & 63;
        *(float4*)&Qs[r * 256 + k4 * 4] =
            *(const float4*)&g_q[base + (size_t)(qt * 64 + r) * DIM + k4 * 4];
    }

    ull o[8][4];                  // packed pairs covering dims 8c..8c+7
    #pragma unroll
    for (int i = 0; i < 8; i++)
        #pragma unroll
        for (int j = 0; j < 4; j++) o[i][j] = 0ull;
    float m[8], l[8];
    #pragma unroll
    for (int i = 0; i < 8; i++) { m[i] = -3.0e38f; l[i] = 0.f; }

    for (int kt = 0; kt < SEQ / 128; kt++) {
        asm volatile("cp.async.wait_group 0;");
        __syncthreads();          // tile kt (and Q on iter 0) visible

        // dense QK: lane computes s[rr][cols c, c+32, c+64, c+96]
        ull acc[8][4];
        #pragma unroll
        for (int rr = 0; rr < 8; rr++)
            #pragma unroll
            for (int j = 0; j < 4; j++) acc[rr][j] = 0ull;

        const float* kp0 = &Ks[c * 256];
        const float* kp1 = &Ks[(c + 32) * 256];   // same xor phase: &7 equal
        const float* kp2 = &Ks[(c + 64) * 256];
        const float* kp3 = &Ks[(c + 96) * 256];
        #pragma unroll 2
        for (int k4 = 0; k4 < 64; k4++) {
            int sc = (k4 ^ cx) << 2;
            ulonglong2 kv0 = *(const ulonglong2*)&kp0[sc];
            ulonglong2 kv1 = *(const ulonglong2*)&kp1[sc];
            ulonglong2 kv2 = *(const ulonglong2*)&kp2[sc];
            ulonglong2 kv3 = *(const ulonglong2*)&kp3[sc];
            #pragma unroll
            for (int rr = 0; rr < 8; rr++) {
                ulonglong2 qv = *(const ulonglong2*)&Qs[(w * 8 + rr) * 256 + k4 * 4];
                acc[rr][0] = ffma2(qv.x, kv0.x, acc[rr][0]);
                acc[rr][0] = ffma2(qv.y, kv0.y, acc[rr][0]);
                acc[rr][1] = ffma2(qv.x, kv1.x, acc[rr][1]);
                acc[rr][1] = ffma2(qv.y, kv1.y, acc[rr][1]);
                acc[rr][2] = ffma2(qv.x, kv2.x, acc[rr][2]);
                acc[rr][2] = ffma2(qv.y, kv2.y, acc[rr][2]);
                acc[rr][3] = ffma2(qv.x, kv3.x, acc[rr][3]);
                acc[rr][3] = ffma2(qv.y, kv3.y, acc[rr][3]);
            }
        }

        __syncthreads();          // all warps done reading Ks
        if (kt + 1 < SEQ / 128)
            load_ktile(kt + 1);   // overlaps the sparse phase below

        // sparse softmax + PV gather, per row (reads only regs + g_v)
        const float* vtile = &g_v[base + (size_t)(kt * 128) * DIM + c * 8];
        #pragma unroll
        for (int rr = 0; rr < 8; rr++) {
            float a, b;
            float s[4];
            upk2(acc[rr][0], a, b); s[0] = (a + b) * 0.0625f;
            upk2(acc[rr][1], a, b); s[1] = (a + b) * 0.0625f;
            upk2(acc[rr][2], a, b); s[2] = (a + b) * 0.0625f;
            upk2(acc[rr][3], a, b); s[3] = (a + b) * 0.0625f;
            float tm = fmaxf(fmaxf(s[0], s[1]), fmaxf(s[2], s[3]));
            #pragma unroll
            for (int off = 16; off > 0; off >>= 1)
                tm = fmaxf(tm, __shfl_xor_sync(0xffffffffu, tm, off));

            if (tm >= m[rr] - 35.0f) {            // warp-uniform
                float nm = fmaxf(m[rr], tm);
                if (nm > m[rr]) {                 // rescale only on max update
                    float fac = __expf(m[rr] - nm);
                    l[rr] *= fac;
                    ull f2 = pk2(fac, fac);
                    o[rr][0] = fmul2(o[rr][0], f2);
                    o[rr][1] = fmul2(o[rr][1], f2);
                    o[rr][2] = fmul2(o[rr][2], f2);
                    o[rr][3] = fmul2(o[rr][3], f2);
                    m[rr] = nm;
                }
                float thr = nm - 35.0f;
                #pragma unroll
                for (int j = 0; j < 4; j++) {
                    unsigned bal = __ballot_sync(0xffffffffu, s[j] >= thr);
                    while (bal) {
                        int ln = __ffs(bal) - 1; bal &= bal - 1;
                        float sv = __shfl_sync(0xffffffffu, s[j], ln);
                        float p = __expf(sv - nm);
                        l[rr] += p;
                        const ulonglong2* vr =
                            (const ulonglong2*)(vtile + (size_t)(ln + j * 32) * DIM);
                        ulonglong2 V0 = vr[0], V1 = vr[1];
                        ull pp = pk2(p, p);
                        o[rr][0] = ffma2(pp, V0.x, o[rr][0]);
                        o[rr][1] = ffma2(pp, V0.y, o[rr][1]);
                        o[rr][2] = ffma2(pp, V1.x, o[rr][2]);
                        o[rr][3] = ffma2(pp, V1.y, o[rr][3]);
                    }
                }
            }
        }
    }

    // ------------------------------------------------------------------
    // fused epilogue: out[r,n] += sum_d o_norm[r,d] * Cw[h*256+d, n]
    // ------------------------------------------------------------------
    const int h = hb >> 3;
    const int out_r0 = (hb & 7) * SEQ + qt * 64 + w * 8;

    float cw[8][8];               // [i dim-in-slice][n]
    const float* cwp = Cw + ((size_t)h * 256 + c * 8) * 8;
    #pragma unroll
    for (int i = 0; i < 8; i++) {
        float4 u0 = *(const float4*)&cwp[i * 8 + 0];
        float4 u1 = *(const float4*)&cwp[i * 8 + 4];
        cw[i][0] = u0.x; cw[i][1] = u0.y; cw[i][2] = u0.z; cw[i][3] = u0.w;
        cw[i][4] = u1.x; cw[i][5] = u1.y; cw[i][6] = u1.z; cw[i][7] = u1.w;
    }

    #pragma unroll
    for (int rr = 0; rr < 8; rr++) {
        float inv = 1.0f / l[rr];
        float v[8];
        upk2(o[rr][0], v[0], v[1]);
        upk2(o[rr][1], v[2], v[3]);
        upk2(o[rr][2], v[4], v[5]);
        upk2(o[rr][3], v[6], v[7]);
        float pn[8] = {};
        #pragma unroll
        for (int i = 0; i < 8; i++) {
            float ov = v[i] * inv;
            #pragma unroll
            for (int n = 0; n < 8; n++)
                pn[n] = fmaf(ov, cw[i][n], pn[n]);
        }
        #pragma unroll
        for (int n = 0; n < 8; n++) {
            #pragma unroll
            for (int off = 16; off > 0; off >>= 1)
                pn[n] += __shfl_xor_sync(0xffffffffu, pn[n], off);
        }
        if (c < 8)
            atomicAdd(&out[(size_t)(out_r0 + rr) * 8 + c], pn[c]);
    }
}

// ---------------------------------------------------------------------------
extern "C" void kernel_launch(void* const* d_in, const int* in_sizes, int n_in,
                              void* d_out, int out_size)
{
    const float* x    = (const float*)d_in[0];
    const float* lstm = (const float*)d_in[1];
    const float* Qw   = (const float*)d_in[2];
    const float* Qb   = (const float*)d_in[3];
    const float* Kw   = (const float*)d_in[4];
    const float* Kb   = (const float*)d_in[5];
    const float* Vw   = (const float*)d_in[6];
    const float* Vb   = (const float*)d_in[7];
    const float* Cw   = (const float*)d_in[8];
    const float* Cb   = (const float*)d_in[9];
    float* out = (float*)d_out;

    cudaFuncSetAttribute(flash_kernel, cudaFuncAttributeMaxDynamicSharedMemorySize, FLASH_SMEM);

    init_out_kernel<<<512, 256>>>(Cb, out);     // out[r,n] = Cb[n]
    proj_kernel<<<dim3(4, 256, 24), dim3(16, 16)>>>(x, lstm, Qw, Qb, Kw, Kb, Vw, Vb);
    flash_kernel<<<dim3(32, 64), 256, FLASH_SMEM>>>(Cw, out);
}